// round 5
// baseline (speedup 1.0000x reference)
#include <cuda_runtime.h>
#include <cstdint>
#include <cstddef>

// Problem constants (fixed by the reference)
#define BB 128
#define TT 2048
#define II 32
#define HH 64
constexpr int NROWS  = BB * TT;        // 262144
constexpr int NELEM  = NROWS * HH;     // 16,777,216 per plane
constexpr int NCHAIN = BB * 2 * HH;    // 16384 scan chains
constexpr int CHK    = 8;              // chunks per chain (scan split)
constexpr int CLEN   = TT / CHK;       // 256

// Scratch (device globals — no runtime allocation allowed).
// xw planes (j-major [b][t][j]) are OVERWRITTEN with prefix sums PS by pass1.
__device__ float g_xw0[NELEM];
__device__ float g_xw1[NELEM];
__device__ float g_h0[NELEM];          // local scan results h_local
__device__ float g_h1[NELEM];
__device__ float g_S  [NCHAIN * CHK];  // per-chunk total sum
__device__ float g_hin[NCHAIN * CHK];  // layout: [(b*2+dir)*8 + chunk][j]

typedef unsigned long long u64;

// ---- packed f32x2 helpers (Blackwell sm_103a) ------------------------------
__device__ __forceinline__ u64 pk2(float lo, float hi) {
    u64 r; asm("mov.b64 %0, {%1, %2};" : "=l"(r) : "f"(lo), "f"(hi)); return r;
}
__device__ __forceinline__ void upk2(u64 v, float& lo, float& hi) {
    asm("mov.b64 {%0, %1}, %2;" : "=f"(lo), "=f"(hi) : "l"(v));
}
__device__ __forceinline__ u64 ffma2(u64 a, u64 b, u64 c) {
    u64 d; asm("fma.rn.f32x2 %0, %1, %2, %3;" : "=l"(d) : "l"(a), "l"(b), "l"(c)); return d;
}

__device__ __forceinline__ bool row_is_identity(const float* W, int j) {
    bool ok = true;
#pragma unroll
    for (int k = 0; k < HH; k++) ok &= (W[j * HH + k] == ((k == j) ? 1.0f : 0.0f));
    return ok;
}

// ============================================================================
// Kernel 1: input projection, j-major output.
// Compute: warp w -> (dir = w>>2, t-group tq = w&3), lane = j-pair. Weights in
// registers (packed), x read as warp-uniform broadcast LDS.128 (1 LDS : 4
// FFMA2). Results bounce through SMEM (pitch-66 u64) -> aligned LDS.128 +
// coalesced STG.128 (4 lines/instr).
// ============================================================================
__global__ __launch_bounds__(256) void proj_kernel(
    const float* __restrict__ x,
    const float* __restrict__ Wihf, const float* __restrict__ Wihb,
    const float* __restrict__ bihf, const float* __restrict__ bhhf,
    const float* __restrict__ bihb, const float* __restrict__ bhhb)
{
    __shared__ __align__(16) float sx[32][32];
    __shared__ __align__(16) u64   sout[32 * 66];   // [t][jpg], pitch 66 u64

    const int tx   = threadIdx.x;
    const int b    = blockIdx.x >> 6;
    const int t0   = (blockIdx.x & 63) * 32;
    const int w    = tx >> 5;
    const int lane = tx & 31;
    const int dir  = w >> 2;
    const int tq   = w & 3;
    const int j0   = lane * 2, j1 = j0 + 1;

    // stage x tile: 32 t-rows x 32 i, coalesced float4
    {
        int r = tx >> 3, c4 = (tx & 7) * 4;
        *(float4*)&sx[r][c4] =
            *(const float4*)&x[(size_t)(b * TT + t0 + r) * II + c4];
    }

    const float* W = dir ? Wihb : Wihf;
    u64 w0[16], w1[16];
#pragma unroll
    for (int m = 0; m < 16; m++) {
        w0[m] = pk2(W[j0 * II + 2 * m], W[j0 * II + 2 * m + 1]);
        w1[m] = pk2(W[j1 * II + 2 * m], W[j1 * II + 2 * m + 1]);
    }
    const float bs0 = dir ? (bihb[j0] + bhhb[j0]) : (bihf[j0] + bhhf[j0]);
    const float bs1 = dir ? (bihb[j1] + bhhb[j1]) : (bihf[j1] + bhhf[j1]);

    __syncthreads();

#pragma unroll
    for (int u = 0; u < 8; u++) {
        const int t = tq * 8 + u;
        const ulonglong2* xp = reinterpret_cast<const ulonglong2*>(&sx[t][0]);
        u64 a0 = 0, a1 = 0;
#pragma unroll
        for (int m = 0; m < 8; m++) {
            ulonglong2 xv = xp[m];               // warp-uniform broadcast
            a0 = ffma2(w0[2 * m],     xv.x, a0);
            a0 = ffma2(w0[2 * m + 1], xv.y, a0);
            a1 = ffma2(w1[2 * m],     xv.x, a1);
            a1 = ffma2(w1[2 * m + 1], xv.y, a1);
        }
        float l0, h0, l1, h1; upk2(a0, l0, h0); upk2(a1, l1, h1);
        sout[t * 66 + dir * 32 + lane] = pk2(l0 + h0 + bs0, l1 + h1 + bs1);
    }
    __syncthreads();

    // coalesced store phase: warp w stores t rows {w, w+8, w+16, w+24}
#pragma unroll
    for (int v = 0; v < 4; v++) {
        const int t   = v * 8 + w;
        const int c32 = lane;
        ulonglong2 p = *(const ulonglong2*)&sout[t * 66 + 2 * c32];
        float f0, f1, f2, f3; upk2(p.x, f0, f1); upk2(p.y, f2, f3);
        const int dd = c32 >> 4, j4 = (c32 & 15) * 4;
        float* plane = dd ? g_xw1 : g_xw0;
        *(float4*)&plane[(size_t)(b * TT + t0 + t) * HH + j4] = make_float4(f0, f1, f2, f3);
    }
}

// ============================================================================
// Scan pass1: per-chunk local scan (h_in = 0) writing h_local into the h
// plane, running prefix sum PS overwriting the xw plane in place, and the
// chunk total into g_S. Fast path requires W_hh == I exactly (per-dir block-
// wide check); general fallback does the full serial matvec scan and leaves
// xw untouched.
// Block map: blk=(b,q); combo=q*4+(tx>>6); dir=combo>>3 (dir-pure blocks),
// chunk=combo&7; j=tx&63 (coalesced).
// ============================================================================
__global__ __launch_bounds__(256) void scan_pass1(
    const float* __restrict__ Whhf, const float* __restrict__ Whhb)
{
    const int blk = blockIdx.x;          // 512
    const int b = blk >> 2, q = blk & 3;
    const int tx = threadIdx.x;
    const int j = tx & 63;
    const int combo = q * 4 + (tx >> 6);
    const int dir = combo >> 3;
    const int chunk = combo & 7;
    const float* W = dir ? Whhb : Whhf;

    __shared__ int sOK;
    if (tx == 0) sOK = 1;
    __syncthreads();
    if (!row_is_identity(W, j)) atomicAnd(&sOK, 0);
    __syncthreads();

    float* xw = dir ? g_xw1 : g_xw0;     // non-const: PS written in place
    float* hp = dir ? g_h1  : g_h0;

    if (sOK) {
        const int tstart = dir ? (TT - 1 - chunk * CLEN) : chunk * CLEN;
        const ptrdiff_t step = dir ? -(ptrdiff_t)HH : (ptrdiff_t)HH;
        float* xq = xw + (size_t)(b * TT + tstart) * HH + j;
        float* hw = hp + (size_t)(b * TT + tstart) * HH + j;
        float h = 0.0f, S = 0.0f;
        for (int g = 0; g < CLEN / 8; g++) {
            float v[8];
#pragma unroll
            for (int u = 0; u < 8; u++) v[u] = xq[step * u];
#pragma unroll
            for (int u = 0; u < 8; u++) {
                S += v[u];
                h = fmaxf(v[u] + h, 0.0f);
                hw[step * u] = h;
                xq[step * u] = S;        // PS overwrite
            }
            xq += step * 8; hw += step * 8;
        }
        g_S[((b * 128 + dir * 64 + j) << 3) + chunk] = S;
    } else {
        // general fallback: one block per (b,dir) does the full serial scan
        if (q != 0 && q != 2) return;
        __shared__ float shv[HH];
        float wrow[HH];
        if (tx < HH) {
#pragma unroll
            for (int k = 0; k < HH; k++) wrow[k] = W[j * HH + k];
            shv[j] = 0.0f;
        }
        __syncthreads();
        for (int t = 0; t < TT; t++) {
            const int tt = dir ? (TT - 1 - t) : t;
            float acc = 0.0f;
            if (tx < HH) {
                acc = xw[(size_t)(b * TT + tt) * HH + j];
#pragma unroll
                for (int k = 0; k < HH; k++) acc += wrow[k] * shv[k];
                acc = fmaxf(acc, 0.0f);
            }
            __syncthreads();
            if (tx < HH) {
                shv[j] = acc;
                hp[(size_t)(b * TT + tt) * HH + j] = acc;
            }
            __syncthreads();
        }
    }
}

// ============================================================================
// Scan pass2: 8-step boundary scan per chain.
// Identity path: h_in[c+1] = max(S_c + h_in_c, h_local_last_c); writes h_in in
// the [(b*2+dir)*8 + c][j] layout (j-contiguous for the MLP's float4 loads).
// General path: writes -1e30 so the MLP fix-up degrades to h_local exactly.
// ============================================================================
__global__ __launch_bounds__(256) void scan_pass2(
    const float* __restrict__ Whhf, const float* __restrict__ Whhb)
{
    const int tx = threadIdx.x;
    const int chain = blockIdx.x * 256 + tx;   // 64 blocks
    const int j = chain & 63, dir = (chain >> 6) & 1, b = chain >> 7;

    __shared__ int sOKd[2];
    if (tx < 2) sOKd[tx] = 1;
    __syncthreads();
    {
        const int cd = (tx >> 6) & 1;
        const float* Wc = cd ? Whhb : Whhf;
        if (!row_is_identity(Wc, tx & 63)) atomicAnd(&sOKd[cd], 0);
    }
    __syncthreads();

    const int hinbase = (b * 16 + dir * 8) * 64 + j;
    if (!sOKd[dir]) {
#pragma unroll
        for (int c = 0; c < CHK; c++) g_hin[hinbase + c * 64] = -1e30f;
        return;
    }

    const float* hp = dir ? g_h1 : g_h0;
    float hin = 0.0f;
#pragma unroll
    for (int c = 0; c < CHK; c++) {
        g_hin[hinbase + c * 64] = hin;
        const int tl = dir ? (TT - 1 - c * CLEN - (CLEN - 1)) : (c * CLEN + CLEN - 1);
        const float hl = hp[(size_t)(b * TT + tl) * HH + j];
        hin = fmaxf(g_S[chain * CHK + c] + hin, hl);
    }
}

// ============================================================================
// Kernel 3: MLP head with inline scan fix-up in the staging phase:
//   h(t,j) = max(PS(t,j) + h_in(chunk,j), h_local(t,j))   (exact; h_local>=PS)
// 16-row tiles. Compute: thread=(kseg, j-pair); rows processed in PAIRS with
// 4 independent FFMA2 accumulator chains for ILP; rotated m-loop keeps the 4
// ksegs in disjoint SMEM bank groups.
// ============================================================================
__global__ __launch_bounds__(256) void mlp_kernel(
    const float* __restrict__ ff0w, const float* __restrict__ ff0b,
    const float* __restrict__ ff1w, const float* __restrict__ ff1b,
    float* __restrict__ out)
{
    __shared__ __align__(16) float shh[16][132];
    __shared__ float sPart[8][16];

    const int tx   = threadIdx.x;
    const int kseg = tx & 3;
    const int jp   = tx >> 2;
    const int j0   = jp * 2, j1 = j0 + 1;
    const int kb   = kseg * 32;
    const int warp = tx >> 5, lane = tx & 31;

    u64 wa[16], wb[16];
#pragma unroll
    for (int m = 0; m < 16; m++) {
        wa[m] = pk2(ff0w[j0 * 128 + kb + 2 * m], ff0w[j0 * 128 + kb + 2 * m + 1]);
        wb[m] = pk2(ff0w[j1 * 128 + kb + 2 * m], ff0w[j1 * 128 + kb + 2 * m + 1]);
    }
    const float b00 = ff0b[j0], b01 = ff0b[j1];
    const float f10 = ff1w[j0], f11 = ff1w[j1];
    const float f1b = ff1b[0];

    // staging map: thread -> (row sr/sr+8, dir, 4-j chunk)
    const int sr   = tx >> 5;
    const int scc  = tx & 31;
    const int sdir = scc >> 4;
    const int sk4  = (scc & 15) * 4;
    const float* hplane  = sdir ? g_h1  : g_h0;
    const float* psplane = sdir ? g_xw1 : g_xw0;

    const int ntiles = NROWS / 16;
    for (int tile = blockIdx.x; tile < ntiles; tile += gridDim.x) {
        const int row0 = tile * 16;
        const int b    = row0 >> 11;              // TT = 2048
        const int t0   = row0 & (TT - 1);
        const int ch0  = t0 >> 8;                 // CLEN = 256
        const int chunk = sdir ? (7 - ch0) : ch0;
        __syncthreads();
        {
            float4 iv = *(const float4*)&g_hin[(b * 16 + sdir * 8 + chunk) * 64 + sk4];
#pragma unroll
            for (int it = 0; it < 2; it++) {
                const int r = sr + it * 8;
                const size_t off = (size_t)(row0 + r) * HH + sk4;
                float4 hv = *(const float4*)&hplane[off];
                float4 pv = *(const float4*)&psplane[off];
                float4 o;
                o.x = fmaxf(pv.x + iv.x, hv.x);
                o.y = fmaxf(pv.y + iv.y, hv.y);
                o.z = fmaxf(pv.z + iv.z, hv.z);
                o.w = fmaxf(pv.w + iv.w, hv.w);
                *(float4*)&shh[r][sdir * 64 + sk4] = o;
            }
        }
        __syncthreads();
#pragma unroll 1
        for (int rp = 0; rp < 8; rp++) {
            const int ra = rp * 2, rb = ra + 1;
            const ulonglong2* hpa = reinterpret_cast<const ulonglong2*>(&shh[ra][kb]);
            const ulonglong2* hpb = reinterpret_cast<const ulonglong2*>(&shh[rb][kb]);
            u64 a00 = 0, a01 = 0, a10 = 0, a11 = 0;
#pragma unroll
            for (int m = 0; m < 8; m++) {
                const int mm = (m + 2 * kseg) & 7;   // bank-group rotation
                ulonglong2 ha = hpa[mm];
                ulonglong2 hb = hpb[mm];
                a00 = ffma2(wa[2 * mm],     ha.x, a00);
                a00 = ffma2(wa[2 * mm + 1], ha.y, a00);
                a01 = ffma2(wb[2 * mm],     ha.x, a01);
                a01 = ffma2(wb[2 * mm + 1], ha.y, a01);
                a10 = ffma2(wa[2 * mm],     hb.x, a10);
                a10 = ffma2(wa[2 * mm + 1], hb.y, a10);
                a11 = ffma2(wb[2 * mm],     hb.x, a11);
                a11 = ffma2(wb[2 * mm + 1], hb.y, a11);
            }
            float p, q;
            upk2(a00, p, q); float z00 = p + q;
            upk2(a01, p, q); float z01 = p + q;
            upk2(a10, p, q); float z10 = p + q;
            upk2(a11, p, q); float z11 = p + q;
            // k-segment combine (lane bits 0,1) — 4 independent chains
            z00 += __shfl_xor_sync(0xffffffffu, z00, 1);
            z01 += __shfl_xor_sync(0xffffffffu, z01, 1);
            z10 += __shfl_xor_sync(0xffffffffu, z10, 1);
            z11 += __shfl_xor_sync(0xffffffffu, z11, 1);
            z00 += __shfl_xor_sync(0xffffffffu, z00, 2);
            z01 += __shfl_xor_sync(0xffffffffu, z01, 2);
            z10 += __shfl_xor_sync(0xffffffffu, z10, 2);
            z11 += __shfl_xor_sync(0xffffffffu, z11, 2);
            z00 += b00; z01 += b01; z10 += b00; z11 += b01;
            float y0 = f10 * (z00 > 0.0f ? z00 : 0.01f * z00)
                     + f11 * (z01 > 0.0f ? z01 : 0.01f * z01);
            float y1 = f10 * (z10 > 0.0f ? z10 : 0.01f * z10)
                     + f11 * (z11 > 0.0f ? z11 : 0.01f * z11);
            // j-pair reduce (bits 2..4) — two independent chains
            y0 += __shfl_xor_sync(0xffffffffu, y0, 4);
            y1 += __shfl_xor_sync(0xffffffffu, y1, 4);
            y0 += __shfl_xor_sync(0xffffffffu, y0, 8);
            y1 += __shfl_xor_sync(0xffffffffu, y1, 8);
            y0 += __shfl_xor_sync(0xffffffffu, y0, 16);
            y1 += __shfl_xor_sync(0xffffffffu, y1, 16);
            if (lane == 0) { sPart[warp][ra] = y0; sPart[warp][rb] = y1; }
        }
        __syncthreads();
        if (tx < 16) {
            float s = 0.0f;
#pragma unroll
            for (int w = 0; w < 8; w++) s += sPart[w][tx];
            out[row0 + tx] = s + f1b;
        }
    }
}

// ============================================================================
extern "C" void kernel_launch(void* const* d_in, const int* in_sizes, int n_in,
                              void* d_out, int out_size)
{
    const float* x    = (const float*)d_in[0];
    const float* Wihf = (const float*)d_in[1];
    const float* Whhf = (const float*)d_in[2];
    const float* bihf = (const float*)d_in[3];
    const float* bhhf = (const float*)d_in[4];
    const float* Wihb = (const float*)d_in[5];
    const float* Whhb = (const float*)d_in[6];
    const float* bihb = (const float*)d_in[7];
    const float* bhhb = (const float*)d_in[8];
    const float* ff0w = (const float*)d_in[9];
    const float* ff0b = (const float*)d_in[10];
    const float* ff1w = (const float*)d_in[11];
    const float* ff1b = (const float*)d_in[12];

    proj_kernel<<<8192, 256>>>(x, Wihf, Wihb, bihf, bhhf, bihb, bhhb);
    scan_pass1<<<512, 256>>>(Whhf, Whhb);
    scan_pass2<<<64, 256>>>(Whhf, Whhb);
    mlp_kernel<<<2048, 256>>>(ff0w, ff0b, ff1w, ff1b, (float*)d_out);
}

// round 7
// speedup vs baseline: 2.2511x; 2.2511x over previous
#include <cuda_runtime.h>
#include <cuda_bf16.h>
#include <cstdint>
#include <cstddef>

// Problem constants (fixed by the reference)
#define BB 128
#define TT 2048
#define II 32
#define HH 64
constexpr int NROWS  = BB * TT;        // 262144
constexpr int NELEM  = NROWS * HH;     // 16,777,216 per plane
constexpr int NCHAIN = BB * 2 * HH;    // 16384 scan chains
constexpr int CHK    = 8;              // chunks per chain (scan split)
constexpr int CLEN   = TT / CHK;       // 256

// Scratch (device globals — no runtime allocation allowed).
__device__ float g_xw0[NELEM];
__device__ float g_xw1[NELEM];
__device__ float g_h0[NELEM];
__device__ float g_h1[NELEM];
__device__ float g_S  [NCHAIN * CHK];
__device__ float g_hin[NCHAIN * CHK];

// Pre-built padded B' image for the MMA MLP: 128 rows x 392 bf16 (pitch 784 B)
constexpr int KB3     = 384;           // split-K: [Whi | Wlo | Whi]
constexpr int BPITCHE = 392;           // elements per row (784 bytes)
__device__ uint32_t g_Bimg[128 * BPITCHE / 2];   // 100352 bytes

typedef unsigned long long u64;

// ---- packed f32x2 helpers ---------------------------------------------------
__device__ __forceinline__ u64 pk2(float lo, float hi) {
    u64 r; asm("mov.b64 %0, {%1, %2};" : "=l"(r) : "f"(lo), "f"(hi)); return r;
}
__device__ __forceinline__ void upk2(u64 v, float& lo, float& hi) {
    asm("mov.b64 {%0, %1}, %2;" : "=f"(lo), "=f"(hi) : "l"(v));
}
__device__ __forceinline__ u64 ffma2(u64 a, u64 b, u64 c) {
    u64 d; asm("fma.rn.f32x2 %0, %1, %2, %3;" : "=l"(d) : "l"(a), "l"(b), "l"(c)); return d;
}
__device__ __forceinline__ u64 add2(u64 a, u64 b) {
    u64 d; asm("add.rn.f32x2 %0, %1, %2;" : "=l"(d) : "l"(a), "l"(b)); return d;
}

__device__ __forceinline__ bool row_is_identity(const float* W, int j) {
    bool ok = true;
#pragma unroll
    for (int k = 0; k < HH; k++) ok &= (W[j * HH + k] == ((k == j) ? 1.0f : 0.0f));
    return ok;
}

__device__ __forceinline__ uint32_t smem_u32(const void* p) {
    uint32_t a;
    asm("{ .reg .u64 t; cvta.to.shared.u64 t, %1; cvt.u32.u64 %0, t; }"
        : "=r"(a) : "l"(p));
    return a;
}

// ============================================================================
// Kernel 1: input projection (R4 version — proven).
// ============================================================================
__global__ __launch_bounds__(256) void proj_kernel(
    const float* __restrict__ x,
    const float* __restrict__ Wihf, const float* __restrict__ Wihb,
    const float* __restrict__ bihf, const float* __restrict__ bhhf,
    const float* __restrict__ bihb, const float* __restrict__ bhhb)
{
    __shared__ float sxT[II][33];
    __shared__ u64   swpk[64][II];
    __shared__ u64   sbias[64];
    __shared__ u64   sout[32 * 65];

    const int tx = threadIdx.x;
    const int b  = blockIdx.x >> 6;
    const int t0 = (blockIdx.x & 63) * 32;

    {
        int tl = tx >> 3, c4 = (tx & 7) * 4;
        float4 v = *(const float4*)&x[(size_t)(b * TT + t0 + tl) * II + c4];
        sxT[c4 + 0][tl] = v.x; sxT[c4 + 1][tl] = v.y;
        sxT[c4 + 2][tl] = v.z; sxT[c4 + 3][tl] = v.w;
    }
    {
        int jpg = tx >> 2, iq = tx & 3;
        const float* W = (jpg >= 32) ? Wihb : Wihf;
        int jl = (jpg & 31) * 2;
        const float* ra = &W[jl * II + iq * 8];
        const float* rb = &W[(jl + 1) * II + iq * 8];
        float4 a0 = *(const float4*)ra, a1 = *(const float4*)(ra + 4);
        float4 b0 = *(const float4*)rb, b1 = *(const float4*)(rb + 4);
        u64* dst = &swpk[jpg][iq * 8];
        dst[0] = pk2(a0.x, b0.x); dst[1] = pk2(a0.y, b0.y);
        dst[2] = pk2(a0.z, b0.z); dst[3] = pk2(a0.w, b0.w);
        dst[4] = pk2(a1.x, b1.x); dst[5] = pk2(a1.y, b1.y);
        dst[6] = pk2(a1.z, b1.z); dst[7] = pk2(a1.w, b1.w);
    }
    if (tx < 64) {
        int dir = tx >> 5, jl = (tx & 31) * 2;
        float s0 = dir ? (bihb[jl]     + bhhb[jl])     : (bihf[jl]     + bhhf[jl]);
        float s1 = dir ? (bihb[jl + 1] + bhhb[jl + 1]) : (bihf[jl + 1] + bhhf[jl + 1]);
        sbias[tx] = pk2(s0, s1);
    }
    __syncthreads();

    const int w = tx >> 5, lane = tx & 31;

    u64 xpk[II];
#pragma unroll
    for (int i = 0; i < II; i++) { float xv = sxT[i][lane]; xpk[i] = pk2(xv, xv); }

#pragma unroll
    for (int it = 0; it < 8; it++) {
        const int jpg = w * 8 + it;
        u64 acca = sbias[jpg];
        u64 accb = 0ull;
#pragma unroll
        for (int i = 0; i < II; i += 2) {
            acca = ffma2(swpk[jpg][i],     xpk[i],     acca);
            accb = ffma2(swpk[jpg][i + 1], xpk[i + 1], accb);
        }
        sout[lane * 65 + jpg] = add2(acca, accb);
    }
    __syncthreads();

#pragma unroll
    for (int v = 0; v < 4; v++) {
        const int t   = v * 8 + w;
        const int c32 = lane;
        u64 lo = sout[t * 65 + 2 * c32];
        u64 hi = sout[t * 65 + 2 * c32 + 1];
        float f0, f1, f2, f3; upk2(lo, f0, f1); upk2(hi, f2, f3);
        const int dir = c32 >> 4, j4 = (c32 & 15) * 4;
        float* plane = dir ? g_xw1 : g_xw0;
        *(float4*)&plane[(size_t)(b * TT + t0 + t) * HH + j4] = make_float4(f0, f1, f2, f3);
    }
}

// ============================================================================
// Scan pass1 / pass2 / pass3 (R4 versions — proven).
// ============================================================================
__global__ __launch_bounds__(256) void scan_pass1(
    const float* __restrict__ Whhf, const float* __restrict__ Whhb)
{
    const int blk = blockIdx.x;
    const int b = blk >> 2, q = blk & 3;
    const int tx = threadIdx.x;
    const int j = tx & 63;
    const int combo = q * 4 + (tx >> 6);
    const int dir = combo >> 3;
    const int chunk = combo & 7;
    const float* W = dir ? Whhb : Whhf;

    __shared__ int sOK;
    if (tx == 0) sOK = 1;
    __syncthreads();
    if (!row_is_identity(W, j)) atomicAnd(&sOK, 0);
    __syncthreads();

    const float* xw = dir ? g_xw1 : g_xw0;
    float*       hp = dir ? g_h1  : g_h0;

    if (sOK) {
        const int tstart = dir ? (TT - 1 - chunk * CLEN) : chunk * CLEN;
        const ptrdiff_t step = dir ? -(ptrdiff_t)HH : (ptrdiff_t)HH;
        const float* xp = xw + (size_t)(b * TT + tstart) * HH + j;
        float*       hw = hp + (size_t)(b * TT + tstart) * HH + j;
        float h = 0.0f, S = 0.0f;
        for (int g = 0; g < CLEN / 8; g++) {
            float v[8];
#pragma unroll
            for (int u = 0; u < 8; u++) v[u] = xp[step * u];
#pragma unroll
            for (int u = 0; u < 8; u++) {
                S += v[u];
                h = fmaxf(v[u] + h, 0.0f);
                hw[step * u] = h;
            }
            xp += step * 8; hw += step * 8;
        }
        g_S[((b * 128 + dir * 64 + j) << 3) + chunk] = S;
    } else {
        if (q != 0 && q != 2) return;
        __shared__ float shv[HH];
        float wrow[HH];
        if (tx < HH) {
#pragma unroll
            for (int k = 0; k < HH; k++) wrow[k] = W[j * HH + k];
            shv[j] = 0.0f;
        }
        __syncthreads();
        for (int t = 0; t < TT; t++) {
            const int tt = dir ? (TT - 1 - t) : t;
            float acc = 0.0f;
            if (tx < HH) {
                acc = xw[(size_t)(b * TT + tt) * HH + j];
#pragma unroll
                for (int k = 0; k < HH; k++) acc += wrow[k] * shv[k];
                acc = fmaxf(acc, 0.0f);
            }
            __syncthreads();
            if (tx < HH) {
                shv[j] = acc;
                hp[(size_t)(b * TT + tt) * HH + j] = acc;
            }
            __syncthreads();
        }
    }
}

__global__ __launch_bounds__(256) void scan_pass2(
    const float* __restrict__ Whhf, const float* __restrict__ Whhb)
{
    const int tx = threadIdx.x;
    const int chain = blockIdx.x * 256 + tx;
    const int j = chain & 63, dir = (chain >> 6) & 1, b = chain >> 7;

    __shared__ int sOKd[2];
    if (tx < 2) sOKd[tx] = 1;
    __syncthreads();
    {
        const int cd = (tx >> 6) & 1;
        const float* Wc = cd ? Whhb : Whhf;
        if (!row_is_identity(Wc, tx & 63)) atomicAnd(&sOKd[cd], 0);
    }
    __syncthreads();
    if (!sOKd[dir]) return;

    const float* hp = dir ? g_h1 : g_h0;
    float hin = 0.0f;
#pragma unroll
    for (int c = 0; c < CHK; c++) {
        g_hin[chain * CHK + c] = hin;
        const int tl = dir ? (TT - 1 - c * CLEN - (CLEN - 1)) : (c * CLEN + CLEN - 1);
        const float hl = hp[(size_t)(b * TT + tl) * HH + j];
        hin = fmaxf(g_S[chain * CHK + c] + hin, hl);
    }
}

__global__ __launch_bounds__(256) void scan_pass3(
    const float* __restrict__ Whhf, const float* __restrict__ Whhb)
{
    const int blk = blockIdx.x;
    const int b = blk >> 2, q = blk & 3;
    const int tx = threadIdx.x;
    const int j = tx & 63;
    const int combo = q * 4 + (tx >> 6);
    const int dir = combo >> 3;
    const int chunk = combo & 7;
    const float* W = dir ? Whhb : Whhf;

    __shared__ int sOK;
    if (tx == 0) sOK = 1;
    __syncthreads();
    if (!row_is_identity(W, j)) atomicAnd(&sOK, 0);
    __syncthreads();
    if (!sOK) return;
    if (chunk == 0) return;

    const int chain = b * 128 + dir * 64 + j;
    const float hin = g_hin[chain * CHK + chunk];
    if (hin == 0.0f) return;

    const float* xw = dir ? g_xw1 : g_xw0;
    float*       hp = dir ? g_h1  : g_h0;
    const int tstart = dir ? (TT - 1 - chunk * CLEN) : chunk * CLEN;
    const ptrdiff_t step = dir ? -(ptrdiff_t)HH : (ptrdiff_t)HH;
    const float* xp = xw + (size_t)(b * TT + tstart) * HH + j;
    float*       hw = hp + (size_t)(b * TT + tstart) * HH + j;
    float S = 0.0f;
    for (int g = 0; g < CLEN / 8; g++) {
        float v[8], hl[8];
#pragma unroll
        for (int u = 0; u < 8; u++) v[u]  = xp[step * u];
#pragma unroll
        for (int u = 0; u < 8; u++) hl[u] = hw[step * u];
#pragma unroll
        for (int u = 0; u < 8; u++) {
            S += v[u];
            hw[step * u] = fmaxf(S + hin, hl[u]);
        }
        xp += step * 8; hw += step * 8;
    }
}

// ============================================================================
// Prep: build padded B' image [128 j][384 k] bf16 (pitch 392 elems).
// K-arrangement [Whi | Wlo | Whi] pairs with A' = [Hhi | Hhi | Hlo].
// ============================================================================
__global__ __launch_bounds__(512) void prep_kernel(const float* __restrict__ ff0w)
{
    const int tx = threadIdx.x;
    const int j  = tx >> 2;          // 128 rows
    const int kq = tx & 3;           // quarter of k-pairs
    for (int kp = kq * 48; kp < (kq + 1) * 48; kp++) {
        const int c = 2 * kp;        // k column (0..382, even)
        int sk, lo_type;
        if (c < 128)      { sk = c;       lo_type = 0; }
        else if (c < 256) { sk = c - 128; lo_type = 1; }
        else              { sk = c - 256; lo_type = 0; }
        float w0 = ff0w[j * 128 + sk], w1 = ff0w[j * 128 + sk + 1];
        __nv_bfloat16 h0 = __float2bfloat16(w0), h1 = __float2bfloat16(w1);
        __nv_bfloat16 o0, o1;
        if (lo_type) {
            o0 = __float2bfloat16(w0 - __bfloat162float(h0));
            o1 = __float2bfloat16(w1 - __bfloat162float(h1));
        } else { o0 = h0; o1 = h1; }
        __nv_bfloat162 p2 = make_bfloat162(o0, o1);
        g_Bimg[j * (BPITCHE / 2) + kp] = *reinterpret_cast<uint32_t*>(&p2);
    }
}

// ============================================================================
// MLP head via warp-level mma.sync (bf16 split, fp32 accum) — base-target ISA.
// Per CTA (256 thr, 8 warps): 128-row tile.
//   A' [128 x 384] bf16 in SMEM, pitch 784 B (row stride mod 128 = 16 ->
//      ldmatrix conflict-free), built from h hi/lo split.
//   B' [128 x 384] bf16 in SMEM, same pitch, copied from g_Bimg.
//   Warp w computes m-tile rows [w*16, w*16+16) x all 128 n via
//   24 k-steps x (ldmatrix.x4 A + 16 x (ldmatrix.x2 B + mma.m16n8k16)).
//   Epilogue: leaky + dot(ff1w) in registers, shfl-reduce lane bits 0,1.
// ============================================================================
constexpr int APITCHB = 784;                 // bytes per A/B row
constexpr int SM_A = 0;
constexpr int SM_B = 128 * APITCHB;          // 100352
constexpr int SM_TOT = SM_B + 128 * APITCHB; // 200704

__global__ __launch_bounds__(256, 1)
void mlp_mma_kernel(const float* __restrict__ ff0b,
                    const float* __restrict__ ff1w,
                    const float* __restrict__ ff1b,
                    float* __restrict__ out)
{
    extern __shared__ __align__(128) char smem[];
    __shared__ float sb0[128], sw1[128];

    const int tx   = threadIdx.x;
    const int wid  = tx >> 5;
    const int lane = tx & 31;
    const int row0 = blockIdx.x * 128;

    // stage bias / ff1 weights
    if (tx < 128) { sb0[tx] = ff0b[tx]; sw1[tx] = ff1w[tx]; }

    // copy B' image (pre-padded): 6272 float4
    {
        const float4* src = reinterpret_cast<const float4*>(g_Bimg);
        float4* dst = reinterpret_cast<float4*>(smem + SM_B);
        for (int i = tx; i < SM_B / 16; i += 256) dst[i] = src[i];
    }

    // build A': thread -> (row r = tx>>1, half = tx&1)
    {
        const int r = tx >> 1, half = tx & 1;
        const float* p0 = &g_h0[(size_t)(row0 + r) * HH];
        const float* p1 = &g_h1[(size_t)(row0 + r) * HH];
        float hv[128];
#pragma unroll
        for (int q = 0; q < 16; q++) *(float4*)&hv[q * 4]      = *(const float4*)&p0[q * 4];
#pragma unroll
        for (int q = 0; q < 16; q++) *(float4*)&hv[64 + q * 4] = *(const float4*)&p1[q * 4];
        char* A = smem + SM_A + r * APITCHB;
        if (half == 0) {
            // k 0..127 = Hhi
#pragma unroll
            for (int kq = 0; kq < 32; kq++) {
                const int c = kq * 4;
                __nv_bfloat162 q0 = make_bfloat162(__float2bfloat16(hv[c]),
                                                   __float2bfloat16(hv[c + 1]));
                __nv_bfloat162 q1 = make_bfloat162(__float2bfloat16(hv[c + 2]),
                                                   __float2bfloat16(hv[c + 3]));
                u64 pq = ((u64)(*reinterpret_cast<uint32_t*>(&q1)) << 32)
                       |  (u64)(*reinterpret_cast<uint32_t*>(&q0));
                *(u64*)(A + c * 2) = pq;
            }
        } else {
            // k 128..255 = Hhi dup, k 256..383 = Hlo
#pragma unroll
            for (int kq = 0; kq < 32; kq++) {
                const int c = kq * 4;
                __nv_bfloat16 b0 = __float2bfloat16(hv[c]);
                __nv_bfloat16 b1 = __float2bfloat16(hv[c + 1]);
                __nv_bfloat16 b2 = __float2bfloat16(hv[c + 2]);
                __nv_bfloat16 b3 = __float2bfloat16(hv[c + 3]);
                __nv_bfloat162 h01 = make_bfloat162(b0, b1);
                __nv_bfloat162 h23 = make_bfloat162(b2, b3);
                u64 hq = ((u64)(*reinterpret_cast<uint32_t*>(&h23)) << 32)
                       |  (u64)(*reinterpret_cast<uint32_t*>(&h01));
                __nv_bfloat162 l01 = make_bfloat162(
                    __float2bfloat16(hv[c]     - __bfloat162float(b0)),
                    __float2bfloat16(hv[c + 1] - __bfloat162float(b1)));
                __nv_bfloat162 l23 = make_bfloat162(
                    __float2bfloat16(hv[c + 2] - __bfloat162float(b2)),
                    __float2bfloat16(hv[c + 3] - __bfloat162float(b3)));
                u64 lq = ((u64)(*reinterpret_cast<uint32_t*>(&l23)) << 32)
                       |  (u64)(*reinterpret_cast<uint32_t*>(&l01));
                *(u64*)(A + (c + 128) * 2) = hq;
                *(u64*)(A + (c + 256) * 2) = lq;
            }
        }
    }
    __syncthreads();

    // ---- warp MMA mainloop ----
    // A addresses: lane&15 -> row within m-tile, lane>>4 -> k-half (8 elems)
    const uint32_t aAddr = smem_u32(smem) + SM_A
        + (uint32_t)(wid * 16 + (lane & 15)) * APITCHB + (uint32_t)(lane >> 4) * 16;
    // B addresses: lane&7 -> n row, lane bit3 -> k-half; lanes 16-31 unused
    const uint32_t bAddr = smem_u32(smem) + SM_B
        + (uint32_t)(lane & 7) * APITCHB + (uint32_t)((lane >> 3) & 1) * 16;

    float c[16][4];
#pragma unroll
    for (int nt = 0; nt < 16; nt++)
#pragma unroll
        for (int q = 0; q < 4; q++) c[nt][q] = 0.0f;

#pragma unroll 1
    for (int kk = 0; kk < 24; kk++) {
        uint32_t a0, a1, a2, a3;
        asm volatile("ldmatrix.sync.aligned.m8n8.x4.shared.b16 {%0,%1,%2,%3}, [%4];"
                     : "=r"(a0), "=r"(a1), "=r"(a2), "=r"(a3)
                     : "r"(aAddr + kk * 32));
#pragma unroll
        for (int nt = 0; nt < 16; nt++) {
            uint32_t b0, b1;
            asm volatile("ldmatrix.sync.aligned.m8n8.x2.shared.b16 {%0,%1}, [%2];"
                         : "=r"(b0), "=r"(b1)
                         : "r"(bAddr + (uint32_t)nt * 8 * APITCHB + kk * 32));
            asm volatile(
                "mma.sync.aligned.m16n8k16.row.col.f32.bf16.bf16.f32 "
                "{%0,%1,%2,%3}, {%4,%5,%6,%7}, {%8,%9}, {%0,%1,%2,%3};"
                : "+f"(c[nt][0]), "+f"(c[nt][1]), "+f"(c[nt][2]), "+f"(c[nt][3])
                : "r"(a0), "r"(a1), "r"(a2), "r"(a3), "r"(b0), "r"(b1));
        }
    }

    // ---- epilogue ----
    // thread holds: rows r0 = l>>2, r1 = r0+8 (of its m-tile);
    // cols nt*8 + (l&3)*2 + {0,1}. Reduce over lane bits 0,1 (the col groups).
    float y0 = 0.0f, y1 = 0.0f;
#pragma unroll
    for (int nt = 0; nt < 16; nt++) {
        const int col = nt * 8 + (lane & 3) * 2;
        const float bb0 = sb0[col], bb1 = sb0[col + 1];
        const float ww0 = sw1[col], ww1 = sw1[col + 1];
        float z;
        z = c[nt][0] + bb0; y0 = fmaf(ww0, z > 0.0f ? z : 0.01f * z, y0);
        z = c[nt][1] + bb1; y0 = fmaf(ww1, z > 0.0f ? z : 0.01f * z, y0);
        z = c[nt][2] + bb0; y1 = fmaf(ww0, z > 0.0f ? z : 0.01f * z, y1);
        z = c[nt][3] + bb1; y1 = fmaf(ww1, z > 0.0f ? z : 0.01f * z, y1);
    }
    y0 += __shfl_xor_sync(0xffffffffu, y0, 1);
    y1 += __shfl_xor_sync(0xffffffffu, y1, 1);
    y0 += __shfl_xor_sync(0xffffffffu, y0, 2);
    y1 += __shfl_xor_sync(0xffffffffu, y1, 2);
    if ((lane & 3) == 0) {
        const float fb = ff1b[0];
        const int r = row0 + wid * 16 + (lane >> 2);
        out[r]     = y0 + fb;
        out[r + 8] = y1 + fb;
    }
}

// ============================================================================
extern "C" void kernel_launch(void* const* d_in, const int* in_sizes, int n_in,
                              void* d_out, int out_size)
{
    const float* x    = (const float*)d_in[0];
    const float* Wihf = (const float*)d_in[1];
    const float* Whhf = (const float*)d_in[2];
    const float* bihf = (const float*)d_in[3];
    const float* bhhf = (const float*)d_in[4];
    const float* Wihb = (const float*)d_in[5];
    const float* Whhb = (const float*)d_in[6];
    const float* bihb = (const float*)d_in[7];
    const float* bhhb = (const float*)d_in[8];
    const float* ff0w = (const float*)d_in[9];
    const float* ff0b = (const float*)d_in[10];
    const float* ff1w = (const float*)d_in[11];
    const float* ff1b = (const float*)d_in[12];

    cudaFuncSetAttribute(mlp_mma_kernel,
                         cudaFuncAttributeMaxDynamicSharedMemorySize, SM_TOT);

    proj_kernel<<<8192, 256>>>(x, Wihf, Wihb, bihf, bhhf, bihb, bhhb);
    scan_pass1<<<512, 256>>>(Whhf, Whhb);
    scan_pass2<<<64, 256>>>(Whhf, Whhb);
    scan_pass3<<<512, 256>>>(Whhf, Whhb);
    prep_kernel<<<1, 512>>>(ff0w);
    mlp_mma_kernel<<<2048, 256, SM_TOT>>>(ff0b, ff1w, ff1b, (float*)d_out);
}

// round 8
// speedup vs baseline: 2.4614x; 1.0934x over previous
#include <cuda_runtime.h>
#include <cuda_bf16.h>
#include <cstdint>
#include <cstddef>

// Problem constants (fixed by the reference)
#define BB 128
#define TT 2048
#define II 32
#define HH 64
constexpr int NROWS  = BB * TT;        // 262144
constexpr int NELEM  = NROWS * HH;     // 16,777,216 per plane
constexpr int NCHAIN = BB * 2 * HH;    // 16384 scan chains
constexpr int CHK    = 8;              // chunks per chain (scan split)
constexpr int CLEN   = TT / CHK;       // 256

// Scratch (device globals — no runtime allocation allowed).
__device__ float g_xw0[NELEM];
__device__ float g_xw1[NELEM];
__device__ float g_h0[NELEM];
__device__ float g_h1[NELEM];
__device__ float g_S  [NCHAIN * CHK];
__device__ float g_hin[NCHAIN * CHK];

// Pre-built padded B' image for the MMA MLP: 128 rows x 392 bf16 (pitch 784 B)
constexpr int KB3     = 384;           // split-K: [Whi | Wlo | Whi]
constexpr int BPITCHE = 392;           // elements per row (784 bytes)
__device__ uint32_t g_Bimg[128 * BPITCHE / 2];   // 100352 bytes

// Pre-built B' image for the MMA projection: 128 rows x 104 bf16 (pitch 208 B)
// row n = dir*64+j; k = [Whi(32) | Wlo(32) | Whi(32)] (pairs A=[xhi|xhi|xlo])
constexpr int PPITCHE = 104;
__device__ uint32_t g_BimgP[128 * PPITCHE / 2];  // 26624 bytes (zero-init pad)
__device__ float    g_biasP[128];                // b_ih + b_hh per (dir,j)

typedef unsigned long long u64;

// ---- packed f32x2 helpers ---------------------------------------------------
__device__ __forceinline__ u64 pk2(float lo, float hi) {
    u64 r; asm("mov.b64 %0, {%1, %2};" : "=l"(r) : "f"(lo), "f"(hi)); return r;
}

__device__ __forceinline__ bool row_is_identity(const float* W, int j) {
    bool ok = true;
#pragma unroll
    for (int k = 0; k < HH; k++) ok &= (W[j * HH + k] == ((k == j) ? 1.0f : 0.0f));
    return ok;
}

__device__ __forceinline__ uint32_t smem_u32(const void* p) {
    uint32_t a;
    asm("{ .reg .u64 t; cvta.to.shared.u64 t, %1; cvt.u32.u64 %0, t; }"
        : "=r"(a) : "l"(p));
    return a;
}

// ============================================================================
// Prep: build both pre-padded B' images + proj bias vector.
// ============================================================================
__global__ __launch_bounds__(512) void prep_kernel(
    const float* __restrict__ ff0w,
    const float* __restrict__ Wihf, const float* __restrict__ Wihb,
    const float* __restrict__ bihf, const float* __restrict__ bhhf,
    const float* __restrict__ bihb, const float* __restrict__ bhhb)
{
    const int tx = threadIdx.x;
    const int j  = tx >> 2;          // 128 rows
    const int kq = tx & 3;

    // --- MLP image: [128 j][384 k], pitch 392 elems ---
    for (int kp = kq * 48; kp < (kq + 1) * 48; kp++) {
        const int c = 2 * kp;
        int sk, lo_type;
        if (c < 128)      { sk = c;       lo_type = 0; }
        else if (c < 256) { sk = c - 128; lo_type = 1; }
        else              { sk = c - 256; lo_type = 0; }
        float w0 = ff0w[j * 128 + sk], w1 = ff0w[j * 128 + sk + 1];
        __nv_bfloat16 h0 = __float2bfloat16(w0), h1 = __float2bfloat16(w1);
        __nv_bfloat16 o0, o1;
        if (lo_type) {
            o0 = __float2bfloat16(w0 - __bfloat162float(h0));
            o1 = __float2bfloat16(w1 - __bfloat162float(h1));
        } else { o0 = h0; o1 = h1; }
        __nv_bfloat162 p2 = make_bfloat162(o0, o1);
        g_Bimg[j * (BPITCHE / 2) + kp] = *reinterpret_cast<uint32_t*>(&p2);
    }

    // --- proj image: [128 n][96 k], pitch 104 elems; n = dir*64 + jrow ---
    {
        const int n = j;
        const int dir = n >> 6, jr = n & 63;
        const float* W = dir ? Wihb : Wihf;
        for (int kp = kq * 12; kp < (kq + 1) * 12; kp++) {
            const int c = 2 * kp;        // 0..94 even
            int sk, lo_type;
            if (c < 32)      { sk = c;      lo_type = 0; }
            else if (c < 64) { sk = c - 32; lo_type = 1; }
            else             { sk = c - 64; lo_type = 0; }
            float w0 = W[jr * II + sk], w1 = W[jr * II + sk + 1];
            __nv_bfloat16 h0 = __float2bfloat16(w0), h1 = __float2bfloat16(w1);
            __nv_bfloat16 o0, o1;
            if (lo_type) {
                o0 = __float2bfloat16(w0 - __bfloat162float(h0));
                o1 = __float2bfloat16(w1 - __bfloat162float(h1));
            } else { o0 = h0; o1 = h1; }
            __nv_bfloat162 p2 = make_bfloat162(o0, o1);
            g_BimgP[n * (PPITCHE / 2) + kp] = *reinterpret_cast<uint32_t*>(&p2);
        }
        if (kq == 0) {
            g_biasP[n] = dir ? (bihb[jr] + bhhb[jr]) : (bihf[jr] + bhhf[jr]);
        }
    }
}

// ============================================================================
// Kernel 1: input projection via mma.sync (bf16 split, fp32 accum).
// Per CTA (256 thr): 128 t-rows x 128 n (dir*64+j).
//   A' [128 x 96] bf16, pitch 208 B, built from x split hi/lo: [xhi|xhi|xlo]
//   B' [128 x 96] bf16, pitch 208 B, copied from g_BimgP: [Whi|Wlo|Whi]
//   6 k-steps x 16 n-tiles mma.m16n8k16. Epilogue adds bias, bounces through
//   SMEM (pitch 132 fl) -> coalesced float4 stores to g_xw0/g_xw1.
// ============================================================================
constexpr int PAPITCH = 208;                        // bytes per A/B row
constexpr int PSM_A   = 0;
constexpr int PSM_B   = 128 * PAPITCH;              // 26624
constexpr int PSM_AB  = PSM_B + 128 * PAPITCH;      // 53248
constexpr int PSM_OUT = 128 * 132 * 4;              // 67584 (overlaps A/B)
constexpr int PSM_TOT = PSM_OUT > PSM_AB ? PSM_OUT : PSM_AB;

__global__ __launch_bounds__(256, 1)
void proj_mma_kernel(const float* __restrict__ x)
{
    extern __shared__ __align__(128) char smem[];
    __shared__ float sbias[128];

    const int tx   = threadIdx.x;
    const int wid  = tx >> 5;
    const int lane = tx & 31;
    const int row0 = blockIdx.x * 128;
    const int b    = row0 >> 11;            // TT = 2048
    const int t0   = row0 & (TT - 1);

    if (tx < 128) sbias[tx] = g_biasP[tx];

    // copy B' image: 1664 float4
    {
        const float4* src = reinterpret_cast<const float4*>(g_BimgP);
        float4* dst = reinterpret_cast<float4*>(smem + PSM_B);
        for (int i = tx; i < PSM_B / 16; i += 256) dst[i] = src[i];
    }

    // build A': thread -> (row r = tx>>1, half = tx&1)
    {
        const int r = tx >> 1, half = tx & 1;
        const float* px = &x[(size_t)(b * TT + t0 + r) * II];
        float hv[II];
#pragma unroll
        for (int q = 0; q < 8; q++) *(float4*)&hv[q * 4] = *(const float4*)&px[q * 4];
        char* A = smem + PSM_A + r * PAPITCH;
        if (half == 0) {
            // k 0..31 = xhi
#pragma unroll
            for (int kq = 0; kq < 8; kq++) {
                const int c = kq * 4;
                __nv_bfloat162 q0 = make_bfloat162(__float2bfloat16(hv[c]),
                                                   __float2bfloat16(hv[c + 1]));
                __nv_bfloat162 q1 = make_bfloat162(__float2bfloat16(hv[c + 2]),
                                                   __float2bfloat16(hv[c + 3]));
                u64 pq = ((u64)(*reinterpret_cast<uint32_t*>(&q1)) << 32)
                       |  (u64)(*reinterpret_cast<uint32_t*>(&q0));
                *(u64*)(A + c * 2) = pq;
            }
        } else {
            // k 32..63 = xhi dup, k 64..95 = xlo
#pragma unroll
            for (int kq = 0; kq < 8; kq++) {
                const int c = kq * 4;
                __nv_bfloat16 b0 = __float2bfloat16(hv[c]);
                __nv_bfloat16 b1 = __float2bfloat16(hv[c + 1]);
                __nv_bfloat16 b2 = __float2bfloat16(hv[c + 2]);
                __nv_bfloat16 b3 = __float2bfloat16(hv[c + 3]);
                __nv_bfloat162 h01 = make_bfloat162(b0, b1);
                __nv_bfloat162 h23 = make_bfloat162(b2, b3);
                u64 hq = ((u64)(*reinterpret_cast<uint32_t*>(&h23)) << 32)
                       |  (u64)(*reinterpret_cast<uint32_t*>(&h01));
                __nv_bfloat162 l01 = make_bfloat162(
                    __float2bfloat16(hv[c]     - __bfloat162float(b0)),
                    __float2bfloat16(hv[c + 1] - __bfloat162float(b1)));
                __nv_bfloat162 l23 = make_bfloat162(
                    __float2bfloat16(hv[c + 2] - __bfloat162float(b2)),
                    __float2bfloat16(hv[c + 3] - __bfloat162float(b3)));
                u64 lq = ((u64)(*reinterpret_cast<uint32_t*>(&l23)) << 32)
                       |  (u64)(*reinterpret_cast<uint32_t*>(&l01));
                *(u64*)(A + (c + 32) * 2) = hq;
                *(u64*)(A + (c + 64) * 2) = lq;
            }
        }
    }
    __syncthreads();

    // ---- warp MMA mainloop ----
    const uint32_t aAddr = smem_u32(smem) + PSM_A
        + (uint32_t)(wid * 16 + (lane & 15)) * PAPITCH + (uint32_t)(lane >> 4) * 16;
    const uint32_t bAddr = smem_u32(smem) + PSM_B
        + (uint32_t)(lane & 7) * PAPITCH + (uint32_t)((lane >> 3) & 1) * 16;

    float c[16][4];
#pragma unroll
    for (int nt = 0; nt < 16; nt++)
#pragma unroll
        for (int q = 0; q < 4; q++) c[nt][q] = 0.0f;

#pragma unroll
    for (int kk = 0; kk < 6; kk++) {
        uint32_t a0, a1, a2, a3;
        asm volatile("ldmatrix.sync.aligned.m8n8.x4.shared.b16 {%0,%1,%2,%3}, [%4];"
                     : "=r"(a0), "=r"(a1), "=r"(a2), "=r"(a3)
                     : "r"(aAddr + kk * 32));
#pragma unroll
        for (int nt = 0; nt < 16; nt++) {
            uint32_t b0, b1;
            asm volatile("ldmatrix.sync.aligned.m8n8.x2.shared.b16 {%0,%1}, [%2];"
                         : "=r"(b0), "=r"(b1)
                         : "r"(bAddr + (uint32_t)nt * 8 * PAPITCH + kk * 32));
            asm volatile(
                "mma.sync.aligned.m16n8k16.row.col.f32.bf16.bf16.f32 "
                "{%0,%1,%2,%3}, {%4,%5,%6,%7}, {%8,%9}, {%0,%1,%2,%3};"
                : "+f"(c[nt][0]), "+f"(c[nt][1]), "+f"(c[nt][2]), "+f"(c[nt][3])
                : "r"(a0), "r"(a1), "r"(a2), "r"(a3), "r"(b0), "r"(b1));
        }
    }
    __syncthreads();   // mainloop reads done; SMEM reused for output bounce

    // ---- epilogue: bias + SMEM bounce (pitch 132 floats) ----
    float* sout = reinterpret_cast<float*>(smem);
    {
        const int r0 = wid * 16 + (lane >> 2);
        const int r1 = r0 + 8;
#pragma unroll
        for (int nt = 0; nt < 16; nt++) {
            const int col = nt * 8 + (lane & 3) * 2;
            const float bb0 = sbias[col], bb1 = sbias[col + 1];
            sout[r0 * 132 + col]     = c[nt][0] + bb0;
            sout[r0 * 132 + col + 1] = c[nt][1] + bb1;
            sout[r1 * 132 + col]     = c[nt][2] + bb0;
            sout[r1 * 132 + col + 1] = c[nt][3] + bb1;
        }
    }
    __syncthreads();

    // coalesced store: 128 t-rows x 32 float4
    for (int i = tx; i < 128 * 32; i += 256) {
        const int t = i >> 5, q = i & 31;
        float4 v = *(const float4*)&sout[t * 132 + q * 4];
        const int dir = q >> 4, j4 = (q & 15) * 4;
        float* plane = dir ? g_xw1 : g_xw0;
        *(float4*)&plane[(size_t)(b * TT + t0 + t) * HH + j4] = v;
    }
}

// ============================================================================
// Scan pass1 / pass2 / pass3 (R4 versions — proven).
// ============================================================================
__global__ __launch_bounds__(256) void scan_pass1(
    const float* __restrict__ Whhf, const float* __restrict__ Whhb)
{
    const int blk = blockIdx.x;
    const int b = blk >> 2, q = blk & 3;
    const int tx = threadIdx.x;
    const int j = tx & 63;
    const int combo = q * 4 + (tx >> 6);
    const int dir = combo >> 3;
    const int chunk = combo & 7;
    const float* W = dir ? Whhb : Whhf;

    __shared__ int sOK;
    if (tx == 0) sOK = 1;
    __syncthreads();
    if (!row_is_identity(W, j)) atomicAnd(&sOK, 0);
    __syncthreads();

    const float* xw = dir ? g_xw1 : g_xw0;
    float*       hp = dir ? g_h1  : g_h0;

    if (sOK) {
        const int tstart = dir ? (TT - 1 - chunk * CLEN) : chunk * CLEN;
        const ptrdiff_t step = dir ? -(ptrdiff_t)HH : (ptrdiff_t)HH;
        const float* xp = xw + (size_t)(b * TT + tstart) * HH + j;
        float*       hw = hp + (size_t)(b * TT + tstart) * HH + j;
        float h = 0.0f, S = 0.0f;
        for (int g = 0; g < CLEN / 8; g++) {
            float v[8];
#pragma unroll
            for (int u = 0; u < 8; u++) v[u] = xp[step * u];
#pragma unroll
            for (int u = 0; u < 8; u++) {
                S += v[u];
                h = fmaxf(v[u] + h, 0.0f);
                hw[step * u] = h;
            }
            xp += step * 8; hw += step * 8;
        }
        g_S[((b * 128 + dir * 64 + j) << 3) + chunk] = S;
    } else {
        if (q != 0 && q != 2) return;
        __shared__ float shv[HH];
        float wrow[HH];
        if (tx < HH) {
#pragma unroll
            for (int k = 0; k < HH; k++) wrow[k] = W[j * HH + k];
            shv[j] = 0.0f;
        }
        __syncthreads();
        for (int t = 0; t < TT; t++) {
            const int tt = dir ? (TT - 1 - t) : t;
            float acc = 0.0f;
            if (tx < HH) {
                acc = xw[(size_t)(b * TT + tt) * HH + j];
#pragma unroll
                for (int k = 0; k < HH; k++) acc += wrow[k] * shv[k];
                acc = fmaxf(acc, 0.0f);
            }
            __syncthreads();
            if (tx < HH) {
                shv[j] = acc;
                hp[(size_t)(b * TT + tt) * HH + j] = acc;
            }
            __syncthreads();
        }
    }
}

__global__ __launch_bounds__(256) void scan_pass2(
    const float* __restrict__ Whhf, const float* __restrict__ Whhb)
{
    const int tx = threadIdx.x;
    const int chain = blockIdx.x * 256 + tx;
    const int j = chain & 63, dir = (chain >> 6) & 1, b = chain >> 7;

    __shared__ int sOKd[2];
    if (tx < 2) sOKd[tx] = 1;
    __syncthreads();
    {
        const int cd = (tx >> 6) & 1;
        const float* Wc = cd ? Whhb : Whhf;
        if (!row_is_identity(Wc, tx & 63)) atomicAnd(&sOKd[cd], 0);
    }
    __syncthreads();
    if (!sOKd[dir]) return;

    const float* hp = dir ? g_h1 : g_h0;
    float hin = 0.0f;
#pragma unroll
    for (int c = 0; c < CHK; c++) {
        g_hin[chain * CHK + c] = hin;
        const int tl = dir ? (TT - 1 - c * CLEN - (CLEN - 1)) : (c * CLEN + CLEN - 1);
        const float hl = hp[(size_t)(b * TT + tl) * HH + j];
        hin = fmaxf(g_S[chain * CHK + c] + hin, hl);
    }
}

__global__ __launch_bounds__(256) void scan_pass3(
    const float* __restrict__ Whhf, const float* __restrict__ Whhb)
{
    const int blk = blockIdx.x;
    const int b = blk >> 2, q = blk & 3;
    const int tx = threadIdx.x;
    const int j = tx & 63;
    const int combo = q * 4 + (tx >> 6);
    const int dir = combo >> 3;
    const int chunk = combo & 7;
    const float* W = dir ? Whhb : Whhf;

    __shared__ int sOK;
    if (tx == 0) sOK = 1;
    __syncthreads();
    if (!row_is_identity(W, j)) atomicAnd(&sOK, 0);
    __syncthreads();
    if (!sOK) return;
    if (chunk == 0) return;

    const int chain = b * 128 + dir * 64 + j;
    const float hin = g_hin[chain * CHK + chunk];
    if (hin == 0.0f) return;

    const float* xw = dir ? g_xw1 : g_xw0;
    float*       hp = dir ? g_h1  : g_h0;
    const int tstart = dir ? (TT - 1 - chunk * CLEN) : chunk * CLEN;
    const ptrdiff_t step = dir ? -(ptrdiff_t)HH : (ptrdiff_t)HH;
    const float* xp = xw + (size_t)(b * TT + tstart) * HH + j;
    float*       hw = hp + (size_t)(b * TT + tstart) * HH + j;
    float S = 0.0f;
    for (int g = 0; g < CLEN / 8; g++) {
        float v[8], hl[8];
#pragma unroll
        for (int u = 0; u < 8; u++) v[u]  = xp[step * u];
#pragma unroll
        for (int u = 0; u < 8; u++) hl[u] = hw[step * u];
#pragma unroll
        for (int u = 0; u < 8; u++) {
            S += v[u];
            hw[step * u] = fmaxf(S + hin, hl[u]);
        }
        xp += step * 8; hw += step * 8;
    }
}

// ============================================================================
// MLP head via warp-level mma.sync (R7 version — proven).
// ============================================================================
constexpr int APITCHB = 784;                 // bytes per A/B row
constexpr int SM_A = 0;
constexpr int SM_B = 128 * APITCHB;          // 100352
constexpr int SM_TOT = SM_B + 128 * APITCHB; // 200704

__global__ __launch_bounds__(256, 1)
void mlp_mma_kernel(const float* __restrict__ ff0b,
                    const float* __restrict__ ff1w,
                    const float* __restrict__ ff1b,
                    float* __restrict__ out)
{
    extern __shared__ __align__(128) char smem[];
    __shared__ float sb0[128], sw1[128];

    const int tx   = threadIdx.x;
    const int wid  = tx >> 5;
    const int lane = tx & 31;
    const int row0 = blockIdx.x * 128;

    if (tx < 128) { sb0[tx] = ff0b[tx]; sw1[tx] = ff1w[tx]; }

    {
        const float4* src = reinterpret_cast<const float4*>(g_Bimg);
        float4* dst = reinterpret_cast<float4*>(smem + SM_B);
        for (int i = tx; i < SM_B / 16; i += 256) dst[i] = src[i];
    }

    {
        const int r = tx >> 1, half = tx & 1;
        const float* p0 = &g_h0[(size_t)(row0 + r) * HH];
        const float* p1 = &g_h1[(size_t)(row0 + r) * HH];
        float hv[128];
#pragma unroll
        for (int q = 0; q < 16; q++) *(float4*)&hv[q * 4]      = *(const float4*)&p0[q * 4];
#pragma unroll
        for (int q = 0; q < 16; q++) *(float4*)&hv[64 + q * 4] = *(const float4*)&p1[q * 4];
        char* A = smem + SM_A + r * APITCHB;
        if (half == 0) {
#pragma unroll
            for (int kq = 0; kq < 32; kq++) {
                const int c = kq * 4;
                __nv_bfloat162 q0 = make_bfloat162(__float2bfloat16(hv[c]),
                                                   __float2bfloat16(hv[c + 1]));
                __nv_bfloat162 q1 = make_bfloat162(__float2bfloat16(hv[c + 2]),
                                                   __float2bfloat16(hv[c + 3]));
                u64 pq = ((u64)(*reinterpret_cast<uint32_t*>(&q1)) << 32)
                       |  (u64)(*reinterpret_cast<uint32_t*>(&q0));
                *(u64*)(A + c * 2) = pq;
            }
        } else {
#pragma unroll
            for (int kq = 0; kq < 32; kq++) {
                const int c = kq * 4;
                __nv_bfloat16 b0 = __float2bfloat16(hv[c]);
                __nv_bfloat16 b1 = __float2bfloat16(hv[c + 1]);
                __nv_bfloat16 b2 = __float2bfloat16(hv[c + 2]);
                __nv_bfloat16 b3 = __float2bfloat16(hv[c + 3]);
                __nv_bfloat162 h01 = make_bfloat162(b0, b1);
                __nv_bfloat162 h23 = make_bfloat162(b2, b3);
                u64 hq = ((u64)(*reinterpret_cast<uint32_t*>(&h23)) << 32)
                       |  (u64)(*reinterpret_cast<uint32_t*>(&h01));
                __nv_bfloat162 l01 = make_bfloat162(
                    __float2bfloat16(hv[c]     - __bfloat162float(b0)),
                    __float2bfloat16(hv[c + 1] - __bfloat162float(b1)));
                __nv_bfloat162 l23 = make_bfloat162(
                    __float2bfloat16(hv[c + 2] - __bfloat162float(b2)),
                    __float2bfloat16(hv[c + 3] - __bfloat162float(b3)));
                u64 lq = ((u64)(*reinterpret_cast<uint32_t*>(&l23)) << 32)
                       |  (u64)(*reinterpret_cast<uint32_t*>(&l01));
                *(u64*)(A + (c + 128) * 2) = hq;
                *(u64*)(A + (c + 256) * 2) = lq;
            }
        }
    }
    __syncthreads();

    const uint32_t aAddr = smem_u32(smem) + SM_A
        + (uint32_t)(wid * 16 + (lane & 15)) * APITCHB + (uint32_t)(lane >> 4) * 16;
    const uint32_t bAddr = smem_u32(smem) + SM_B
        + (uint32_t)(lane & 7) * APITCHB + (uint32_t)((lane >> 3) & 1) * 16;

    float c[16][4];
#pragma unroll
    for (int nt = 0; nt < 16; nt++)
#pragma unroll
        for (int q = 0; q < 4; q++) c[nt][q] = 0.0f;

#pragma unroll 1
    for (int kk = 0; kk < 24; kk++) {
        uint32_t a0, a1, a2, a3;
        asm volatile("ldmatrix.sync.aligned.m8n8.x4.shared.b16 {%0,%1,%2,%3}, [%4];"
                     : "=r"(a0), "=r"(a1), "=r"(a2), "=r"(a3)
                     : "r"(aAddr + kk * 32));
#pragma unroll
        for (int nt = 0; nt < 16; nt++) {
            uint32_t b0, b1;
            asm volatile("ldmatrix.sync.aligned.m8n8.x2.shared.b16 {%0,%1}, [%2];"
                         : "=r"(b0), "=r"(b1)
                         : "r"(bAddr + (uint32_t)nt * 8 * APITCHB + kk * 32));
            asm volatile(
                "mma.sync.aligned.m16n8k16.row.col.f32.bf16.bf16.f32 "
                "{%0,%1,%2,%3}, {%4,%5,%6,%7}, {%8,%9}, {%0,%1,%2,%3};"
                : "+f"(c[nt][0]), "+f"(c[nt][1]), "+f"(c[nt][2]), "+f"(c[nt][3])
                : "r"(a0), "r"(a1), "r"(a2), "r"(a3), "r"(b0), "r"(b1));
        }
    }

    float y0 = 0.0f, y1 = 0.0f;
#pragma unroll
    for (int nt = 0; nt < 16; nt++) {
        const int col = nt * 8 + (lane & 3) * 2;
        const float bb0 = sb0[col], bb1 = sb0[col + 1];
        const float ww0 = sw1[col], ww1 = sw1[col + 1];
        float z;
        z = c[nt][0] + bb0; y0 = fmaf(ww0, z > 0.0f ? z : 0.01f * z, y0);
        z = c[nt][1] + bb1; y0 = fmaf(ww1, z > 0.0f ? z : 0.01f * z, y0);
        z = c[nt][2] + bb0; y1 = fmaf(ww0, z > 0.0f ? z : 0.01f * z, y1);
        z = c[nt][3] + bb1; y1 = fmaf(ww1, z > 0.0f ? z : 0.01f * z, y1);
    }
    y0 += __shfl_xor_sync(0xffffffffu, y0, 1);
    y1 += __shfl_xor_sync(0xffffffffu, y1, 1);
    y0 += __shfl_xor_sync(0xffffffffu, y0, 2);
    y1 += __shfl_xor_sync(0xffffffffu, y1, 2);
    if ((lane & 3) == 0) {
        const float fb = ff1b[0];
        const int r = row0 + wid * 16 + (lane >> 2);
        out[r]     = y0 + fb;
        out[r + 8] = y1 + fb;
    }
}

// ============================================================================
extern "C" void kernel_launch(void* const* d_in, const int* in_sizes, int n_in,
                              void* d_out, int out_size)
{
    const float* x    = (const float*)d_in[0];
    const float* Wihf = (const float*)d_in[1];
    const float* Whhf = (const float*)d_in[2];
    const float* bihf = (const float*)d_in[3];
    const float* bhhf = (const float*)d_in[4];
    const float* Wihb = (const float*)d_in[5];
    const float* Whhb = (const float*)d_in[6];
    const float* bihb = (const float*)d_in[7];
    const float* bhhb = (const float*)d_in[8];
    const float* ff0w = (const float*)d_in[9];
    const float* ff0b = (const float*)d_in[10];
    const float* ff1w = (const float*)d_in[11];
    const float* ff1b = (const float*)d_in[12];

    cudaFuncSetAttribute(mlp_mma_kernel,
                         cudaFuncAttributeMaxDynamicSharedMemorySize, SM_TOT);
    cudaFuncSetAttribute(proj_mma_kernel,
                         cudaFuncAttributeMaxDynamicSharedMemorySize, PSM_TOT);

    prep_kernel<<<1, 512>>>(ff0w, Wihf, Wihb, bihf, bhhf, bihb, bhhb);
    proj_mma_kernel<<<2048, 256, PSM_TOT>>>(x);
    scan_pass1<<<512, 256>>>(Whhf, Whhb);
    scan_pass2<<<64, 256>>>(Whhf, Whhb);
    scan_pass3<<<512, 256>>>(Whhf, Whhb);
    mlp_mma_kernel<<<2048, 256, SM_TOT>>>(ff0b, ff1w, ff1b, (float*)d_out);
}